// round 16
// baseline (speedup 1.0000x reference)
#include <cuda_runtime.h>
#include <cuda_bf16.h>
#include <cstdint>

#define BB 16
#define NW 100
#define HH 8
#define LLEN 64
#define CC 256
#define DH 32
#define LOGIT_MAX 4.6051701859880913680f
#define X_TOTAL (BB*NW*LLEN*CC)

#define RSTRIDE 144          // bytes per staged row: 4 groups x [16B hi | 16B lo] + 16B pad
#define TBYTES (LLEN * RSTRIDE)

__device__ __forceinline__ uint32_t smem_u32(const void* p) {
    uint32_t a;
    asm("{ .reg .u64 t; cvta.to.shared.u64 t, %1; cvt.u32.u64 %0, t; }" : "=r"(a) : "l"(p));
    return a;
}

__device__ __forceinline__ uint32_t pack2(float a, float b) {
    __nv_bfloat162 h = __floats2bfloat162_rn(a, b);
    return *reinterpret_cast<uint32_t*>(&h);
}
__device__ __forceinline__ float2 unpack2(uint32_t u) {
    return __bfloat1622float2(*reinterpret_cast<__nv_bfloat162*>(&u));
}

__device__ __forceinline__ void split4(float4 xv, uint2& hi, uint2& lo) {
    hi.x = pack2(xv.x, xv.y);
    hi.y = pack2(xv.z, xv.w);
    float2 f01 = unpack2(hi.x);
    float2 f23 = unpack2(hi.y);
    lo.x = pack2(xv.x - f01.x, xv.y - f01.y);
    lo.y = pack2(xv.z - f23.x, xv.w - f23.y);
}

__device__ __forceinline__ void mma16816(float* c, const uint32_t* a,
                                         uint32_t b0, uint32_t b1) {
    asm volatile(
        "mma.sync.aligned.m16n8k16.row.col.f32.bf16.bf16.f32 "
        "{%0,%1,%2,%3}, {%4,%5,%6,%7}, {%8,%9}, {%0,%1,%2,%3};"
        : "+f"(c[0]), "+f"(c[1]), "+f"(c[2]), "+f"(c[3])
        : "r"(a[0]), "r"(a[1]), "r"(a[2]), "r"(a[3]), "r"(b0), "r"(b1));
}

__device__ __forceinline__ void ldsm4(uint32_t* r, uint32_t addr) {
    asm volatile("ldmatrix.sync.aligned.m8n8.x4.shared.b16 {%0,%1,%2,%3}, [%4];"
                 : "=r"(r[0]), "=r"(r[1]), "=r"(r[2]), "=r"(r[3]) : "r"(addr));
}
__device__ __forceinline__ void ldsm4t(uint32_t* r, uint32_t addr) {
    asm volatile("ldmatrix.sync.aligned.m8n8.x4.trans.shared.b16 {%0,%1,%2,%3}, [%4];"
                 : "=r"(r[0]), "=r"(r[1]), "=r"(r[2]), "=r"(r[3]) : "r"(addr));
}

// lane address: 16x16 tile at (row0, col group g0 = 8-col units), hi/lo select
__device__ __forceinline__ uint32_t tadr(uint32_t base, int lane, int r0, int g0, int hl) {
    int mat = lane >> 3, lr = lane & 7;
    return base + (uint32_t)(r0 + lr + ((mat & 1) << 3)) * RSTRIDE
                + (uint32_t)(g0 + (mat >> 1)) * 32 + hl * 16;
}

// K row perm inverse: true row n -> staged position (j<<3)|(t<<1)|d
__device__ __forceinline__ int prK(int n) {
    int j = (((n >> 4) & 3) << 1) | ((n >> 1) & 1);
    return (j << 3) | (((n >> 2) & 3) << 1) | (n & 1);
}
// V row perm inverse: true row n = [kk|t|e|d] -> staged [kk|e|t|d]
__device__ __forceinline__ int prV(int n) {
    return (n & 0x30) | (((n >> 1) & 1) << 3) | (((n >> 2) & 3) << 1) | (n & 1);
}

__global__ __launch_bounds__(128, 7)
void tat_hmma_kernel(const float* __restrict__ q, const float* __restrict__ k,
                     const float* __restrict__ v, const float* __restrict__ pos,
                     const float* __restrict__ ls, float* __restrict__ out)
{
    __shared__ __align__(16) char SM[3 * TBYTES];
    char* Qs = SM;
    char* Ks = SM + TBYTES;
    char* Vs = SM + 2 * TBYTES;

    const int h   = blockIdx.x;
    const int w0  = blockIdx.y * 2;
    const int b   = blockIdx.z;
    const int tid = threadIdx.x;
    const int wid = tid >> 5;
    const int lane = tid & 31;
    const int g = lane >> 2;
    const int t = lane & 3;

    const uint32_t sQ = smem_u32(Qs), sK = smem_u32(Ks), sV = smem_u32(Vs);
    const int m0 = wid * 16;
    const int r0 = m0 + g;
    const int r1 = r0 + 8;

    const float sc = __expf(fminf(__ldg(ls + h), LOGIT_MAX));
    const float* pb = pos + ((long)(b * HH + h) * LLEN) * LLEN;

    #pragma unroll 1
    for (int wi = 0; wi < 2; wi++) {
        const int w = w0 + wi;
        const long qkvbase = (long)(b * NW + w) * LLEN * CC;
        const float* qh = q + qkvbase + h * DH;
        const float* kh = k + qkvbase + h * DH;
        const float* vh = v + qkvbase + h * DH;

        if (wi) __syncthreads();   // prior window's smem reads complete

        // ---- stage Q (identity rows), K (perm rows), V (perm rows) ----
        #pragma unroll
        for (int i = 0; i < 4; i++) {
            int idx = tid + 128 * i;         // 0..511
            int r  = idx >> 3;               // 0..63
            int c4 = (idx & 7) * 4;          // 0..28
            uint32_t coff = (uint32_t)((c4 >> 3) * 32 + ((c4 & 4) << 1));
            float4 qv = *(const float4*)(qh + (long)r * CC + c4);
            float4 kv = *(const float4*)(kh + (long)r * CC + c4);
            float4 vv = *(const float4*)(vh + (long)r * CC + c4);
            uint2 hi, lo;
            split4(qv, hi, lo);
            { char* p = Qs + (uint32_t)r * RSTRIDE + coff;
              *(uint2*)p = hi; *(uint2*)(p + 16) = lo; }
            split4(kv, hi, lo);
            { char* p = Ks + (uint32_t)prK(r) * RSTRIDE + coff;
              *(uint2*)p = hi; *(uint2*)(p + 16) = lo; }
            split4(vv, hi, lo);
            { char* p = Vs + (uint32_t)prV(r) * RSTRIDE + coff;
              *(uint2*)p = hi; *(uint2*)(p + 16) = lo; }
        }
        __syncthreads();

        // ---- S = Q K^T (64x64x32), warp owns rows m0..m0+15 ----
        uint32_t aH[2][4], aL[2][4];
        #pragma unroll
        for (int ks = 0; ks < 2; ks++) {
            ldsm4(aH[ks], tadr(sQ, lane, m0, 2 * ks, 0));
            ldsm4(aL[ks], tadr(sQ, lane, m0, 2 * ks, 1));
        }

        float s[8][4];
        #pragma unroll
        for (int j = 0; j < 8; j++)
            #pragma unroll
            for (int c = 0; c < 4; c++) s[j][c] = 0.0f;

        #pragma unroll
        for (int nt = 0; nt < 4; nt++) {
            uint32_t bh[2][4], bl[2][4];
            #pragma unroll
            for (int ks = 0; ks < 2; ks++) {
                ldsm4(bh[ks], tadr(sK, lane, nt * 16, 2 * ks, 0));
                ldsm4(bl[ks], tadr(sK, lane, nt * 16, 2 * ks, 1));
            }
            const int j0 = 2 * nt, j1 = 2 * nt + 1;
            #pragma unroll
            for (int ks = 0; ks < 2; ks++) {
                mma16816(s[j0], aH[ks], bh[ks][0], bh[ks][2]);
                mma16816(s[j1], aH[ks], bh[ks][1], bh[ks][3]);
                mma16816(s[j0], aH[ks], bl[ks][0], bl[ks][2]);
                mma16816(s[j1], aH[ks], bl[ks][1], bl[ks][3]);
                mma16816(s[j0], aL[ks], bh[ks][0], bh[ks][2]);
                mma16816(s[j1], aL[ks], bh[ks][1], bh[ks][3]);
            }
        }

        // ---- scale + position (contiguous float4 via col perm) + softmax ----
        float mx0 = -1e30f, mx1 = -1e30f;
        #pragma unroll
        for (int qd = 0; qd < 4; qd++) {
            const int j0 = 2 * qd, j1 = 2 * qd + 1;
            const int c0 = 16 * qd + 4 * t;
            float4 p0 = *(const float4*)(pb + r0 * LLEN + c0);
            float4 p1 = *(const float4*)(pb + r1 * LLEN + c0);
            s[j0][0] = fmaf(s[j0][0], sc, p0.x);
            s[j0][1] = fmaf(s[j0][1], sc, p0.y);
            s[j1][0] = fmaf(s[j1][0], sc, p0.z);
            s[j1][1] = fmaf(s[j1][1], sc, p0.w);
            s[j0][2] = fmaf(s[j0][2], sc, p1.x);
            s[j0][3] = fmaf(s[j0][3], sc, p1.y);
            s[j1][2] = fmaf(s[j1][2], sc, p1.z);
            s[j1][3] = fmaf(s[j1][3], sc, p1.w);
            mx0 = fmaxf(mx0, fmaxf(fmaxf(s[j0][0], s[j0][1]), fmaxf(s[j1][0], s[j1][1])));
            mx1 = fmaxf(mx1, fmaxf(fmaxf(s[j0][2], s[j0][3]), fmaxf(s[j1][2], s[j1][3])));
        }
        mx0 = fmaxf(mx0, __shfl_xor_sync(0xffffffffu, mx0, 1));
        mx0 = fmaxf(mx0, __shfl_xor_sync(0xffffffffu, mx0, 2));
        mx1 = fmaxf(mx1, __shfl_xor_sync(0xffffffffu, mx1, 1));
        mx1 = fmaxf(mx1, __shfl_xor_sync(0xffffffffu, mx1, 2));

        float sum0 = 0.0f, sum1 = 0.0f;
        #pragma unroll
        for (int j = 0; j < 8; j++) {
            s[j][0] = __expf(s[j][0] - mx0);
            s[j][1] = __expf(s[j][1] - mx0);
            s[j][2] = __expf(s[j][2] - mx1);
            s[j][3] = __expf(s[j][3] - mx1);
            sum0 += s[j][0] + s[j][1];
            sum1 += s[j][2] + s[j][3];
        }
        sum0 += __shfl_xor_sync(0xffffffffu, sum0, 1);
        sum0 += __shfl_xor_sync(0xffffffffu, sum0, 2);
        sum1 += __shfl_xor_sync(0xffffffffu, sum1, 1);
        sum1 += __shfl_xor_sync(0xffffffffu, sum1, 2);
        const float inv0 = __fdividef(1.0f, sum0);
        const float inv1 = __fdividef(1.0f, sum1);

        // normalize + write attn (contiguous float4 per thread)
        float* attn = out + X_TOTAL + ((long)((b * NW + w) * HH + h)) * (LLEN * LLEN);
        #pragma unroll
        for (int qd = 0; qd < 4; qd++) {
            const int j0 = 2 * qd, j1 = 2 * qd + 1;
            const int c0 = 16 * qd + 4 * t;
            s[j0][0] *= inv0; s[j0][1] *= inv0; s[j1][0] *= inv0; s[j1][1] *= inv0;
            s[j0][2] *= inv1; s[j0][3] *= inv1; s[j1][2] *= inv1; s[j1][3] *= inv1;
            *(float4*)(attn + r0 * LLEN + c0) =
                make_float4(s[j0][0], s[j0][1], s[j1][0], s[j1][1]);
            *(float4*)(attn + r1 * LLEN + c0) =
                make_float4(s[j0][2], s[j0][3], s[j1][2], s[j1][3]);
        }

        // ---- repack P fragments (C-layout == A-layout under the V row perm) ----
        uint32_t pHi[4][4], pLo[4][4];
        #pragma unroll
        for (int kk = 0; kk < 4; kk++) {
            const int j0 = 2 * kk, j1 = 2 * kk + 1;
            float2 f;
            pHi[kk][0] = pack2(s[j0][0], s[j0][1]);
            f = unpack2(pHi[kk][0]); pLo[kk][0] = pack2(s[j0][0] - f.x, s[j0][1] - f.y);
            pHi[kk][1] = pack2(s[j0][2], s[j0][3]);
            f = unpack2(pHi[kk][1]); pLo[kk][1] = pack2(s[j0][2] - f.x, s[j0][3] - f.y);
            pHi[kk][2] = pack2(s[j1][0], s[j1][1]);
            f = unpack2(pHi[kk][2]); pLo[kk][2] = pack2(s[j1][0] - f.x, s[j1][1] - f.y);
            pHi[kk][3] = pack2(s[j1][2], s[j1][3]);
            f = unpack2(pHi[kk][3]); pLo[kk][3] = pack2(s[j1][2] - f.x, s[j1][3] - f.y);
        }

        // ---- O = P V; V fragments via ldmatrix.trans ----
        float* xo = out + qkvbase + h * DH;
        #pragma unroll
        for (int dt = 0; dt < 2; dt++) {
            float o0[4] = {0.f, 0.f, 0.f, 0.f};
            float o1[4] = {0.f, 0.f, 0.f, 0.f};
            #pragma unroll
            for (int ks = 0; ks < 4; ks++) {
                uint32_t vhf[4], vlf[4];
                ldsm4t(vhf, tadr(sV, lane, ks * 16, 2 * dt, 0));
                ldsm4t(vlf, tadr(sV, lane, ks * 16, 2 * dt, 1));
                mma16816(o0, pHi[ks], vhf[0], vhf[1]);
                mma16816(o1, pHi[ks], vhf[2], vhf[3]);
                mma16816(o0, pHi[ks], vlf[0], vlf[1]);
                mma16816(o1, pHi[ks], vlf[2], vlf[3]);
                mma16816(o0, pLo[ks], vhf[0], vhf[1]);
                mma16816(o1, pLo[ks], vhf[2], vhf[3]);
            }
            const int d0 = dt * 16 + t * 2;
            *(float2*)(xo + (long)r0 * CC + d0)     = make_float2(o0[0], o0[1]);
            *(float2*)(xo + (long)r1 * CC + d0)     = make_float2(o0[2], o0[3]);
            *(float2*)(xo + (long)r0 * CC + d0 + 8) = make_float2(o1[0], o1[1]);
            *(float2*)(xo + (long)r1 * CC + d0 + 8) = make_float2(o1[2], o1[3]);
        }
    }
}

extern "C" void kernel_launch(void* const* d_in, const int* in_sizes, int n_in,
                              void* d_out, int out_size)
{
    const float* q   = (const float*)d_in[0];
    const float* k   = (const float*)d_in[1];
    const float* v   = (const float*)d_in[2];
    const float* pos = (const float*)d_in[3];
    const float* ls  = (const float*)d_in[4];
    float* out = (float*)d_out;

    dim3 grid(HH, NW / 2, BB);   // 6400 CTAs, 2 windows each (serial, no overlap)
    tat_hmma_kernel<<<grid, 128>>>(q, k, v, pos, ls, out);
}

// round 17
// speedup vs baseline: 1.0737x; 1.0737x over previous
#include <cuda_runtime.h>
#include <cuda_bf16.h>
#include <cstdint>

#define BB 16
#define NW 100
#define HH 8
#define LLEN 64
#define CC 256
#define DH 32
#define LOGIT_MAX 4.6051701859880913680f
#define X_TOTAL (BB*NW*LLEN*CC)

#define RSTRIDE 144          // bytes per staged row: 4 groups x [16B hi | 16B lo] + 16B pad
#define TBYTES (LLEN * RSTRIDE)

__device__ __forceinline__ uint32_t smem_u32(const void* p) {
    uint32_t a;
    asm("{ .reg .u64 t; cvta.to.shared.u64 t, %1; cvt.u32.u64 %0, t; }" : "=r"(a) : "l"(p));
    return a;
}

__device__ __forceinline__ uint32_t pack2(float a, float b) {
    __nv_bfloat162 h = __floats2bfloat162_rn(a, b);
    return *reinterpret_cast<uint32_t*>(&h);
}
__device__ __forceinline__ float2 unpack2(uint32_t u) {
    return __bfloat1622float2(*reinterpret_cast<__nv_bfloat162*>(&u));
}

__device__ __forceinline__ void split4(float4 xv, uint2& hi, uint2& lo) {
    hi.x = pack2(xv.x, xv.y);
    hi.y = pack2(xv.z, xv.w);
    float2 f01 = unpack2(hi.x);
    float2 f23 = unpack2(hi.y);
    lo.x = pack2(xv.x - f01.x, xv.y - f01.y);
    lo.y = pack2(xv.z - f23.x, xv.w - f23.y);
}

__device__ __forceinline__ void mma16816(float* c, const uint32_t* a,
                                         uint32_t b0, uint32_t b1) {
    asm volatile(
        "mma.sync.aligned.m16n8k16.row.col.f32.bf16.bf16.f32 "
        "{%0,%1,%2,%3}, {%4,%5,%6,%7}, {%8,%9}, {%0,%1,%2,%3};"
        : "+f"(c[0]), "+f"(c[1]), "+f"(c[2]), "+f"(c[3])
        : "r"(a[0]), "r"(a[1]), "r"(a[2]), "r"(a[3]), "r"(b0), "r"(b1));
}

__device__ __forceinline__ void ldsm4(uint32_t* r, uint32_t addr) {
    asm volatile("ldmatrix.sync.aligned.m8n8.x4.shared.b16 {%0,%1,%2,%3}, [%4];"
                 : "=r"(r[0]), "=r"(r[1]), "=r"(r[2]), "=r"(r[3]) : "r"(addr));
}
__device__ __forceinline__ void ldsm4t(uint32_t* r, uint32_t addr) {
    asm volatile("ldmatrix.sync.aligned.m8n8.x4.trans.shared.b16 {%0,%1,%2,%3}, [%4];"
                 : "=r"(r[0]), "=r"(r[1]), "=r"(r[2]), "=r"(r[3]) : "r"(addr));
}

// lane address: 16x16 tile at (row0, col group g0 = 8-col units), hi/lo select
__device__ __forceinline__ uint32_t tadr(uint32_t base, int lane, int r0, int g0, int hl) {
    int mat = lane >> 3, lr = lane & 7;
    return base + (uint32_t)(r0 + lr + ((mat & 1) << 3)) * RSTRIDE
                + (uint32_t)(g0 + (mat >> 1)) * 32 + hl * 16;
}

// K row perm inverse: true row n -> staged position (j<<3)|(t<<1)|d
__device__ __forceinline__ int prK(int n) {
    int j = (((n >> 4) & 3) << 1) | ((n >> 1) & 1);
    return (j << 3) | (((n >> 2) & 3) << 1) | (n & 1);
}
// V row perm inverse: true row n = [kk|t|e|d] -> staged [kk|e|t|d]
__device__ __forceinline__ int prV(int n) {
    return (n & 0x30) | (((n >> 1) & 1) << 3) | (((n >> 2) & 3) << 1) | (n & 1);
}

__global__ __launch_bounds__(128)
void tat_hmma_kernel(const float* __restrict__ q, const float* __restrict__ k,
                     const float* __restrict__ v, const float* __restrict__ pos,
                     const float* __restrict__ ls, float* __restrict__ out)
{
    __shared__ __align__(16) char SM[3 * TBYTES];
    char* Qs = SM;
    char* Ks = SM + TBYTES;
    char* Vs = SM + 2 * TBYTES;

    const int h   = blockIdx.x;
    const int w   = blockIdx.y;
    const int b   = blockIdx.z;
    const int tid = threadIdx.x;
    const int wid = tid >> 5;
    const int lane = tid & 31;
    const int g = lane >> 2;
    const int t = lane & 3;

    const long qkvbase = (long)(b * NW + w) * LLEN * CC;
    const float* qh = q + qkvbase + h * DH;
    const float* kh = k + qkvbase + h * DH;
    const float* vh = v + qkvbase + h * DH;

    // ---- stage Q (identity rows), K (perm rows), V (perm rows) ----
    #pragma unroll
    for (int i = 0; i < 4; i++) {
        int idx = tid + 128 * i;         // 0..511
        int r  = idx >> 3;               // 0..63
        int c4 = (idx & 7) * 4;          // 0..28
        uint32_t coff = (uint32_t)((c4 >> 3) * 32 + ((c4 & 4) << 1));
        float4 qv = *(const float4*)(qh + (long)r * CC + c4);
        float4 kv = *(const float4*)(kh + (long)r * CC + c4);
        float4 vv = *(const float4*)(vh + (long)r * CC + c4);
        uint2 hi, lo;
        split4(qv, hi, lo);
        { char* p = Qs + (uint32_t)r * RSTRIDE + coff;
          *(uint2*)p = hi; *(uint2*)(p + 16) = lo; }
        split4(kv, hi, lo);
        { char* p = Ks + (uint32_t)prK(r) * RSTRIDE + coff;
          *(uint2*)p = hi; *(uint2*)(p + 16) = lo; }
        split4(vv, hi, lo);
        { char* p = Vs + (uint32_t)prV(r) * RSTRIDE + coff;
          *(uint2*)p = hi; *(uint2*)(p + 16) = lo; }
    }
    __syncthreads();

    const uint32_t sQ = smem_u32(Qs), sK = smem_u32(Ks), sV = smem_u32(Vs);

    // ---- S = Q K^T (64x64x32), warp owns rows m0..m0+15 ----
    const int m0 = wid * 16;
    const int r0 = m0 + g;
    const int r1 = r0 + 8;

    uint32_t aH[2][4], aL[2][4];
    #pragma unroll
    for (int ks = 0; ks < 2; ks++) {
        ldsm4(aH[ks], tadr(sQ, lane, m0, 2 * ks, 0));
        ldsm4(aL[ks], tadr(sQ, lane, m0, 2 * ks, 1));
    }

    float s[8][4];
    #pragma unroll
    for (int j = 0; j < 8; j++)
        #pragma unroll
        for (int c = 0; c < 4; c++) s[j][c] = 0.0f;

    #pragma unroll
    for (int nt = 0; nt < 4; nt++) {
        uint32_t bh[2][4], bl[2][4];
        #pragma unroll
        for (int ks = 0; ks < 2; ks++) {
            ldsm4(bh[ks], tadr(sK, lane, nt * 16, 2 * ks, 0));
            ldsm4(bl[ks], tadr(sK, lane, nt * 16, 2 * ks, 1));
        }
        const int j0 = 2 * nt, j1 = 2 * nt + 1;
        #pragma unroll
        for (int ks = 0; ks < 2; ks++) {
            mma16816(s[j0], aH[ks], bh[ks][0], bh[ks][2]);
            mma16816(s[j1], aH[ks], bh[ks][1], bh[ks][3]);
            mma16816(s[j0], aH[ks], bl[ks][0], bl[ks][2]);
            mma16816(s[j1], aH[ks], bl[ks][1], bl[ks][3]);
            mma16816(s[j0], aL[ks], bh[ks][0], bh[ks][2]);
            mma16816(s[j1], aL[ks], bh[ks][1], bh[ks][3]);
        }
    }

    // ---- scale + position (contiguous float4 via col perm) + softmax ----
    const float sc = __expf(fminf(__ldg(ls + h), LOGIT_MAX));
    const float* pb = pos + ((long)(b * HH + h) * LLEN) * LLEN;

    float mx0 = -1e30f, mx1 = -1e30f;
    #pragma unroll
    for (int qd = 0; qd < 4; qd++) {
        const int j0 = 2 * qd, j1 = 2 * qd + 1;
        const int c0 = 16 * qd + 4 * t;
        float4 p0 = *(const float4*)(pb + r0 * LLEN + c0);
        float4 p1 = *(const float4*)(pb + r1 * LLEN + c0);
        s[j0][0] = fmaf(s[j0][0], sc, p0.x);
        s[j0][1] = fmaf(s[j0][1], sc, p0.y);
        s[j1][0] = fmaf(s[j1][0], sc, p0.z);
        s[j1][1] = fmaf(s[j1][1], sc, p0.w);
        s[j0][2] = fmaf(s[j0][2], sc, p1.x);
        s[j0][3] = fmaf(s[j0][3], sc, p1.y);
        s[j1][2] = fmaf(s[j1][2], sc, p1.z);
        s[j1][3] = fmaf(s[j1][3], sc, p1.w);
        mx0 = fmaxf(mx0, fmaxf(fmaxf(s[j0][0], s[j0][1]), fmaxf(s[j1][0], s[j1][1])));
        mx1 = fmaxf(mx1, fmaxf(fmaxf(s[j0][2], s[j0][3]), fmaxf(s[j1][2], s[j1][3])));
    }
    mx0 = fmaxf(mx0, __shfl_xor_sync(0xffffffffu, mx0, 1));
    mx0 = fmaxf(mx0, __shfl_xor_sync(0xffffffffu, mx0, 2));
    mx1 = fmaxf(mx1, __shfl_xor_sync(0xffffffffu, mx1, 1));
    mx1 = fmaxf(mx1, __shfl_xor_sync(0xffffffffu, mx1, 2));

    float sum0 = 0.0f, sum1 = 0.0f;
    #pragma unroll
    for (int j = 0; j < 8; j++) {
        s[j][0] = __expf(s[j][0] - mx0);
        s[j][1] = __expf(s[j][1] - mx0);
        s[j][2] = __expf(s[j][2] - mx1);
        s[j][3] = __expf(s[j][3] - mx1);
        sum0 += s[j][0] + s[j][1];
        sum1 += s[j][2] + s[j][3];
    }
    sum0 += __shfl_xor_sync(0xffffffffu, sum0, 1);
    sum0 += __shfl_xor_sync(0xffffffffu, sum0, 2);
    sum1 += __shfl_xor_sync(0xffffffffu, sum1, 1);
    sum1 += __shfl_xor_sync(0xffffffffu, sum1, 2);
    const float inv0 = __fdividef(1.0f, sum0);
    const float inv1 = __fdividef(1.0f, sum1);

    // normalize + write attn directly as float4 (contiguous per thread)
    float* attn = out + X_TOTAL + ((long)((b * NW + w) * HH + h)) * (LLEN * LLEN);
    #pragma unroll
    for (int qd = 0; qd < 4; qd++) {
        const int j0 = 2 * qd, j1 = 2 * qd + 1;
        const int c0 = 16 * qd + 4 * t;
        s[j0][0] *= inv0; s[j0][1] *= inv0; s[j1][0] *= inv0; s[j1][1] *= inv0;
        s[j0][2] *= inv1; s[j0][3] *= inv1; s[j1][2] *= inv1; s[j1][3] *= inv1;
        *(float4*)(attn + r0 * LLEN + c0) =
            make_float4(s[j0][0], s[j0][1], s[j1][0], s[j1][1]);
        *(float4*)(attn + r1 * LLEN + c0) =
            make_float4(s[j0][2], s[j0][3], s[j1][2], s[j1][3]);
    }

    // ---- repack P fragments (C-layout == A-layout under the V row perm) ----
    uint32_t pHi[4][4], pLo[4][4];
    #pragma unroll
    for (int kk = 0; kk < 4; kk++) {
        const int j0 = 2 * kk, j1 = 2 * kk + 1;
        float2 f;
        pHi[kk][0] = pack2(s[j0][0], s[j0][1]);
        f = unpack2(pHi[kk][0]); pLo[kk][0] = pack2(s[j0][0] - f.x, s[j0][1] - f.y);
        pHi[kk][1] = pack2(s[j0][2], s[j0][3]);
        f = unpack2(pHi[kk][1]); pLo[kk][1] = pack2(s[j0][2] - f.x, s[j0][3] - f.y);
        pHi[kk][2] = pack2(s[j1][0], s[j1][1]);
        f = unpack2(pHi[kk][2]); pLo[kk][2] = pack2(s[j1][0] - f.x, s[j1][1] - f.y);
        pHi[kk][3] = pack2(s[j1][2], s[j1][3]);
        f = unpack2(pHi[kk][3]); pLo[kk][3] = pack2(s[j1][2] - f.x, s[j1][3] - f.y);
    }

    // ---- O = P V; V fragments via ldmatrix.trans ----
    float* xo = out + qkvbase + h * DH;
    #pragma unroll
    for (int dt = 0; dt < 2; dt++) {
        float o0[4] = {0.f, 0.f, 0.f, 0.f};
        float o1[4] = {0.f, 0.f, 0.f, 0.f};
        #pragma unroll
        for (int ks = 0; ks < 4; ks++) {
            uint32_t vhf[4], vlf[4];
            ldsm4t(vhf, tadr(sV, lane, ks * 16, 2 * dt, 0));
            ldsm4t(vlf, tadr(sV, lane, ks * 16, 2 * dt, 1));
            mma16816(o0, pHi[ks], vhf[0], vhf[1]);
            mma16816(o1, pHi[ks], vhf[2], vhf[3]);
            mma16816(o0, pHi[ks], vlf[0], vlf[1]);
            mma16816(o1, pHi[ks], vlf[2], vlf[3]);
            mma16816(o0, pLo[ks], vhf[0], vhf[1]);
            mma16816(o1, pLo[ks], vhf[2], vhf[3]);
        }
        const int d0 = dt * 16 + t * 2;
        *(float2*)(xo + (long)r0 * CC + d0)     = make_float2(o0[0], o0[1]);
        *(float2*)(xo + (long)r1 * CC + d0)     = make_float2(o0[2], o0[3]);
        *(float2*)(xo + (long)r0 * CC + d0 + 8) = make_float2(o1[0], o1[1]);
        *(float2*)(xo + (long)r1 * CC + d0 + 8) = make_float2(o1[2], o1[3]);
    }
}

extern "C" void kernel_launch(void* const* d_in, const int* in_sizes, int n_in,
                              void* d_out, int out_size)
{
    const float* q   = (const float*)d_in[0];
    const float* k   = (const float*)d_in[1];
    const float* v   = (const float*)d_in[2];
    const float* pos = (const float*)d_in[3];
    const float* ls  = (const float*)d_in[4];
    float* out = (float*)d_out;

    dim3 grid(HH, NW, BB);   // 12800 CTAs of 128 threads
    tat_hmma_kernel<<<grid, 128>>>(q, k, v, pos, ls, out);
}